// round 9
// baseline (speedup 1.0000x reference)
#include <cuda_runtime.h>

// out[b,c,h,w] = (1/256) * sum_{p,o in 0..8} inp[b, p*9+o, h, w] * sec[b, c, h+p-4, w+o-4]
// B=8, C=256, H=W=128.
// R6 compute geometry (4ch x 8px per thread, NT=256) with per-p weight
// double-buffering from L2 -> smem 110.8KB -> 2 CTAs/SM.

#define MD 4
#define NTAPS 81
#define HH 128
#define WW 128
#define CC 256

#define TH 8
#define TW 32
#define CB 32                    // channels staged per iteration
#define NCB (CC/CB)              // 8
#define NCH 4                    // channels per thread
#define NT 256

#define WSTR 36                  // weight plane row stride (144B)
#define WPLANE (TH*WSTR)         // 288 floats
#define WBUF (9*WPLANE)          // 2592 floats: 9 o-planes for one p
#define SSTR 44                  // sec row stride (176B)
#define SPLANE (16*SSTR)         // 704 floats / channel
#define S_OFF (2*WBUF)           // sec starts after the two weight buffers
#define SMEM_FLOATS (2*WBUF + CB*SPLANE)        // 27712
#define SMEM_BYTES (SMEM_FLOATS*4)              // 110848 B

typedef unsigned long long u64;

__device__ __forceinline__ u64 pack2(float a, float b) {
    u64 r; asm("mov.b64 %0,{%1,%2};" : "=l"(r) : "f"(a), "f"(b)); return r;
}
__device__ __forceinline__ void ffma2(u64& acc, u64 a, u64 b) {
    asm("fma.rn.f32x2 %0, %1, %2, %0;" : "+l"(acc) : "l"(a), "l"(b));
}
__device__ __forceinline__ u64 fmul2(u64 a, u64 b) {
    u64 r; asm("mul.rn.f32x2 %0, %1, %2;" : "=l"(r) : "l"(a), "l"(b)); return r;
}
__device__ __forceinline__ float lo32(u64 a) { return __uint_as_float((unsigned)(a & 0xffffffffull)); }
__device__ __forceinline__ float hi32(u64 a) { return __uint_as_float((unsigned)(a >> 32)); }

__global__ void __launch_bounds__(NT, 2)
corr_transpose_kernel(const float* __restrict__ inp,
                      const float* __restrict__ sec,
                      float* __restrict__ out)
{
    extern __shared__ float smem[];
    // smem: [2][9 planes][8 rows][36]  weight double buffer
    //       [32 ch][16 rows][44]       sec tile with halo
    float* ssm = smem + S_OFF;

    const int tid = threadIdx.x;
    const int tx  = tid & 3;            // pixel col group (8 px each)
    const int ty  = (tid >> 2) & 7;     // pixel row
    const int cs  = tid >> 5;           // channel subgroup 0..7 (4 ch each)
    const int gx  = blockIdx.x * TW;
    const int gy  = blockIdx.y * TH;
    const int b   = blockIdx.z;

    const float* winp = inp + ((size_t)b * NTAPS * HH + gy) * WW + gx;

    // stage weights for row p into buffer buf (9 o-planes, 576 float4)
    auto stage_w = [&](int buf, int p) {
        #pragma unroll
        for (int s = 0; s < 3; s++) {
            int idx = tid + s * NT;
            if (idx < 576) {
                int col4 = idx & 7;
                int row  = (idx >> 3) & 7;
                int o    = idx >> 6;
                float4 v = *(const float4*)(winp + ((size_t)(p * 9 + o) * HH + row) * WW + col4 * 4);
                *(float4*)(smem + buf * WBUF + o * WPLANE + row * WSTR + col4 * 4) = v;
            }
        }
    };

    stage_w(0, 0);   // prologue: p=0 weights into buffer 0

    const float* sbase = ssm + (cs * NCH) * SPLANE + ty * SSTR + 8 * tx;
    const u64 scale2 = pack2(1.0f / (float)CC, 1.0f / (float)CC);

    int cur = 0;     // buffer holding weights for the upcoming p

    for (int cb = 0; cb < NCB; cb++) {
        __syncthreads();   // previous compute done; prologue/rotated weights staged

        // ---- stage 32 channels of sec with halo: 2 (ch,row) slots per thread ----
        #pragma unroll
        for (int s = 0; s < 2; s++) {
            int slot = tid + s * NT;
            int srow_t = slot & 15;
            int sch    = slot >> 4;
            const float* gsec = sec + ((size_t)(b * CC + cb * CB + sch) * HH) * WW;
            float* plane = ssm + sch * SPLANE;
            int r = gy + srow_t - MD;
            #pragma unroll
            for (int c4 = 0; c4 < 10; c4++) {
                int c = gx - MD + 4 * c4;
                float4 v = make_float4(0.f, 0.f, 0.f, 0.f);
                if ((unsigned)r < HH) {
                    if (c >= 0 && c <= WW - 4) {
                        v = *(const float4*)(gsec + (size_t)r * WW + c);
                    } else {
                        const float* gr = gsec + (size_t)r * WW;
                        if ((unsigned)(c + 0) < WW) v.x = gr[c + 0];
                        if ((unsigned)(c + 1) < WW) v.y = gr[c + 1];
                        if ((unsigned)(c + 2) < WW) v.z = gr[c + 2];
                        if ((unsigned)(c + 3) < WW) v.w = gr[c + 3];
                    }
                }
                *(float4*)(plane + srow_t * SSTR + 4 * c4) = v;
            }
        }
        __syncthreads();

        u64 acc[NCH][4];
        #pragma unroll
        for (int j = 0; j < NCH; j++)
            #pragma unroll
            for (int k = 0; k < 4; k++) acc[j][k] = 0ull;

        #pragma unroll 1
        for (int p = 0; p < 9; p++) {
            // stage next weights into the other buffer (next p, or p=0 of next cb)
            if (p < 8)          stage_w(cur ^ 1, p + 1);
            else if (cb < NCB-1) stage_w(cur ^ 1, 0);

            // ---- compute p from buffer cur ----
            const float* wb = smem + cur * WBUF + ty * WSTR + 8 * tx;
            u64 wp[9][4];
            #pragma unroll
            for (int o = 0; o < 9; o++) {
                const ulonglong2* q = (const ulonglong2*)(wb + o * WPLANE);
                ulonglong2 q0 = q[0];
                ulonglong2 q1 = q[1];
                wp[o][0] = q0.x; wp[o][1] = q0.y;
                wp[o][2] = q1.x; wp[o][3] = q1.y;
            }
            #pragma unroll
            for (int j = 0; j < NCH; j++) {
                const float4* srow = (const float4*)(sbase + j * SPLANE + p * SSTR);
                float4 v0 = srow[0];
                float4 v1 = srow[1];
                float4 v2 = srow[2];
                float4 v3 = srow[3];
                u64 A[8] = { pack2(v0.x,v0.y), pack2(v0.z,v0.w), pack2(v1.x,v1.y), pack2(v1.z,v1.w),
                             pack2(v2.x,v2.y), pack2(v2.z,v2.w), pack2(v3.x,v3.y), pack2(v3.z,v3.w) };
                u64 M[7] = { pack2(v0.y,v0.z), pack2(v0.w,v1.x), pack2(v1.y,v1.z), pack2(v1.w,v2.x),
                             pack2(v2.y,v2.z), pack2(v2.w,v3.x), pack2(v3.y,v3.z) };
                #pragma unroll
                for (int o = 0; o < 9; o++) {
                    if ((o & 1) == 0) {
                        #pragma unroll
                        for (int k = 0; k < 4; k++) ffma2(acc[j][k], wp[o][k], A[(o >> 1) + k]);
                    } else {
                        #pragma unroll
                        for (int k = 0; k < 4; k++) ffma2(acc[j][k], wp[o][k], M[(o >> 1) + k]);
                    }
                }
            }
            __syncthreads();   // staged buffer ready; cur free for overwrite
            cur ^= 1;
        }

        // ---- store 4 channels x 8 px ----
        #pragma unroll
        for (int j = 0; j < NCH; j++) {
            int c = cb * CB + cs * NCH + j;
            float* optr = out + (((size_t)(b * CC + c) * HH + gy + ty) * WW + gx + 8 * tx);
            u64 r0 = fmul2(acc[j][0], scale2);
            u64 r1 = fmul2(acc[j][1], scale2);
            u64 r2 = fmul2(acc[j][2], scale2);
            u64 r3 = fmul2(acc[j][3], scale2);
            *(float4*)(optr)     = make_float4(lo32(r0), hi32(r0), lo32(r1), hi32(r1));
            *(float4*)(optr + 4) = make_float4(lo32(r2), hi32(r2), lo32(r3), hi32(r3));
        }
    }
}

extern "C" void kernel_launch(void* const* d_in, const int* in_sizes, int n_in,
                              void* d_out, int out_size)
{
    const float* inp = (const float*)d_in[0];   // [B, 81, 128, 128]
    const float* sec = (const float*)d_in[1];   // [B, 256, 128, 128]
    float* out = (float*)d_out;                 // [B, 256, 128, 128]

    const int B = in_sizes[0] / (NTAPS * HH * WW);

    cudaFuncSetAttribute(corr_transpose_kernel,
                         cudaFuncAttributeMaxDynamicSharedMemorySize, SMEM_BYTES);

    dim3 grid(WW / TW, HH / TH, B);   // (4, 16, 8)
    corr_transpose_kernel<<<grid, NT, SMEM_BYTES>>>(inp, sec, out);
}

// round 11
// speedup vs baseline: 1.1198x; 1.1198x over previous
#include <cuda_runtime.h>
#include <cstdint>

// out[b,c,h,w] = (1/256) * sum_{p,o in 0..8} inp[b, p*9+o, h, w] * sec[b, c, h+p-4, w+o-4]
// B=8, C=256, H=W=128.
// Tensor formulation with legacy mma.sync (tf32, m16n8k8) — per (h, 16px tile):
//   D[128ch, 16px] += sum_p A_row[128ch, 24win] @ Bband_p[24win, 16px]
// banded at 8-px n-tile granularity (2 k-frags per n-tile per p).

#define HH 128
#define WW 128
#define CC 256
#define MD 4
#define HW (HH*WW)

#define NT 256
#define RSLOT (8*3*512)          // ring slot: 8 ch-blocks x 3 k-frags x 512B = 12288
#define RING_BYTES (10*RSLOT)    // 122880
#define B_OFF RING_BYTES
#define BBYTES (9*2*512)         // 9216 per buffer (9 p x 2 n-tiles x 512B)
#define SMEM_BYTES (B_OFF + 2*BBYTES)   // 141312

static __device__ __forceinline__ uint32_t f2tf(float f) {
    uint32_t r; asm("cvt.rna.tf32.f32 %0, %1;" : "=r"(r) : "f"(f)); return r;
}

static __device__ __forceinline__ void mma8(float* d, const uint4& a, uint32_t b0, uint32_t b1) {
    asm volatile("mma.sync.aligned.m16n8k8.row.col.f32.tf32.tf32.f32 "
                 "{%0,%1,%2,%3}, {%4,%5,%6,%7}, {%8,%9}, {%0,%1,%2,%3};"
                 : "+f"(d[0]), "+f"(d[1]), "+f"(d[2]), "+f"(d[3])
                 : "r"(a.x), "r"(a.y), "r"(a.z), "r"(a.w), "r"(b0), "r"(b1));
}

__global__ void __launch_bounds__(NT, 1)
corr_mma_kernel(const float* __restrict__ inp,
                const float* __restrict__ sec,
                float* __restrict__ out)
{
    extern __shared__ char smem[];
    const int tid  = threadIdx.x;
    const int wid  = tid >> 5;
    const int lane = tid & 31;
    const int w0   = blockIdx.x * 16;
    const int c0   = blockIdx.y * 128;
    const int b    = blockIdx.z;

    // ---- stage sec row r into ring slot r%10, fragment-order layout ----
    // consumer lane l of ch-block cb, k-frag s reads float4 = (a0,a1,a2,a3):
    //   a0 = A[ch=16cb+l/4][k=8s+l%4], a1 = ch+8, a2 = k+4, a3 = both.
    auto stageA = [&](int r) {
        #pragma unroll
        for (int i = 0; i < 3; i++) {
            int idx = tid + i * NT;            // 768 = 8cb x 3s x 32l
            int l  = idx & 31;
            int s  = (idx >> 5) % 3;
            int cb = idx / 96;
            int ch = cb * 16 + (l >> 2);
            int px = w0 - 4 + s * 8 + (l & 3);
            const float* base = sec + ((size_t)(b * CC + c0 + ch) * HH + r) * WW;
            float f0 = 0.f, f1 = 0.f, f2 = 0.f, f3 = 0.f;
            if ((unsigned)px < WW)       { f0 = __ldg(base + px);     f1 = __ldg(base + 8 * HW + px); }
            if ((unsigned)(px + 4) < WW) { f2 = __ldg(base + px + 4); f3 = __ldg(base + 8 * HW + px + 4); }
            uint4 v = make_uint4(f2tf(f0), f2tf(f1), f2tf(f2), f2tf(f3));
            *(uint4*)(smem + (r % 10) * RSLOT + (cb * 3 + s) * 512 + l * 16) = v;
        }
    };

    // ---- build banded B tiles for output row hb into buffer bufsel ----
    // block (p, nt): lane l float4 = (b0,b1 of s=nt ; b0,b1 of s=nt+1)
    //   value(k,x) = inp[p*9 + (k-x)] at px w0+x, zero outside band.
    auto buildB = [&](int hb, int bufsel) {
        #pragma unroll
        for (int i = 0; i < 3; i++) {
            int idx = tid + i * NT;            // 576 = 9p x 2nt x 32l
            if (idx < 576) {
                int l  = idx & 31;
                int nt = (idx >> 5) & 1;
                int p  = idx >> 6;
                int x  = 8 * nt + (l >> 2);
                int o0 = (l & 3) - (l >> 2);   // k(s=nt) - x
                const float* ib = inp + ((size_t)(b * 81 + p * 9) * HH + hb) * WW + (w0 + x);
                float g0 = ((unsigned)(o0)      <= 8u) ? __ldg(ib + (ptrdiff_t)(o0)      * HW) : 0.f;
                float g1 = ((unsigned)(o0 + 4)  <= 8u) ? __ldg(ib + (ptrdiff_t)(o0 + 4)  * HW) : 0.f;
                float g2 = ((unsigned)(o0 + 8)  <= 8u) ? __ldg(ib + (ptrdiff_t)(o0 + 8)  * HW) : 0.f;
                float g3 = ((unsigned)(o0 + 12) <= 8u) ? __ldg(ib + (ptrdiff_t)(o0 + 12) * HW) : 0.f;
                uint4 v = make_uint4(f2tf(g0), f2tf(g1), f2tf(g2), f2tf(g3));
                *(uint4*)(smem + B_OFF + bufsel * BBYTES + idx * 16) = v;
            }
        }
    };

    // prologue: sec rows 0..4, B for h=0 into buffer 0
    for (int r = 0; r < 5; r++) stageA(r);
    buildB(0, 0);
    __syncthreads();

    const unsigned aoff_warp = (unsigned)(wid * 3 * 512 + lane * 16);
    const unsigned boff_lane = (unsigned)(lane * 16);
    const float sc = 1.0f / (float)CC;

    #pragma unroll 1
    for (int h = 0; h < HH; h++) {
        const int buf = h & 1;

        // ---- compute: warp = 16ch x 16px (2 n-tiles), accumulate over p ----
        float acc0[4] = {0.f, 0.f, 0.f, 0.f};
        float acc1[4] = {0.f, 0.f, 0.f, 0.f};
        #pragma unroll
        for (int p = 0; p < 9; p++) {
            int r = h + p - MD;
            if ((unsigned)r < (unsigned)HH) {
                const char* ab = smem + (r % 10) * RSLOT + aoff_warp;
                uint4 A0 = *(const uint4*)(ab);
                uint4 A1 = *(const uint4*)(ab + 512);
                uint4 A2 = *(const uint4*)(ab + 1024);
                const char* bb = smem + B_OFF + buf * BBYTES + p * 1024 + boff_lane;
                uint4 B0 = *(const uint4*)(bb);
                uint4 B1 = *(const uint4*)(bb + 512);
                mma8(acc0, A0, B0.x, B0.y);   // nt=0, s=0
                mma8(acc0, A1, B0.z, B0.w);   // nt=0, s=1
                mma8(acc1, A1, B1.x, B1.y);   // nt=1, s=1
                mma8(acc1, A2, B1.z, B1.w);   // nt=1, s=2
            }
        }

        // ---- epilogue: scale + store (D frag: row=l/4(+8), col=2*(l%4)(+1)) ----
        {
            int cho = c0 + wid * 16 + (lane >> 2);
            float* ob = out + ((size_t)(b * CC + cho) * HH + h) * WW + w0 + 2 * (lane & 3);
            *(float2*)(ob)              = make_float2(acc0[0] * sc, acc0[1] * sc);
            *(float2*)(ob + 8 * HW)     = make_float2(acc0[2] * sc, acc0[3] * sc);
            *(float2*)(ob + 8)          = make_float2(acc1[0] * sc, acc1[1] * sc);
            *(float2*)(ob + 8 * HW + 8) = make_float2(acc1[2] * sc, acc1[3] * sc);
        }

        // ---- stage ahead: sec row h+5, B for h+1 ----
        if (h + 5 < HH) stageA(h + 5);
        if (h + 1 < HH) buildB(h + 1, buf ^ 1);
        __syncthreads();
    }
}

extern "C" void kernel_launch(void* const* d_in, const int* in_sizes, int n_in,
                              void* d_out, int out_size)
{
    const float* inp = (const float*)d_in[0];   // [B, 81, 128, 128]
    const float* sec = (const float*)d_in[1];   // [B, 256, 128, 128]
    float* out = (float*)d_out;                 // [B, 256, 128, 128]

    const int B = in_sizes[0] / (81 * HH * WW);

    cudaFuncSetAttribute(corr_mma_kernel,
                         cudaFuncAttributeMaxDynamicSharedMemorySize, SMEM_BYTES);

    dim3 grid(WW / 16, CC / 128, B);   // (8, 2, 8) = 128 CTAs
    corr_mma_kernel<<<grid, NT, SMEM_BYTES>>>(inp, sec, out);
}

// round 12
// speedup vs baseline: 1.1747x; 1.0490x over previous
#include <cuda_runtime.h>
#include <cstdint>

// out[b,c,h,w] = (1/256) * sum_{p,o in 0..8} inp[b, p*9+o, h, w] * sec[b, c, h+p-4, w+o-4]
// B=8, C=256, H=W=128.
// mma.sync m16n8k8 tf32. CTA = 64ch x 16px x all h. 8 warps: warp = 16ch x 8px.
// smem 78KB -> 2 CTAs/SM, 256 CTAs = 1 wave.

#define HH 128
#define WW 128
#define CC 256
#define MD 4
#define HW (HH*WW)

#define NT 256
#define MCH 64
#define RSLOT (4*3*512)          // ring slot: 4 ch-blocks x 3 k-frags x 512B = 6144
#define RING_BYTES (10*RSLOT)    // 61440
#define B_OFF RING_BYTES
#define BBYTES (9*2*512)         // 9216 per buffer (9 p x 2 n-tiles x 512B)
#define SMEM_BYTES (B_OFF + 2*BBYTES)   // 79872

static __device__ __forceinline__ uint32_t f2tf(float f) {
    uint32_t r; asm("cvt.rna.tf32.f32 %0, %1;" : "=r"(r) : "f"(f)); return r;
}

static __device__ __forceinline__ void mma8(float* d, const uint4& a, uint32_t b0, uint32_t b1) {
    asm volatile("mma.sync.aligned.m16n8k8.row.col.f32.tf32.tf32.f32 "
                 "{%0,%1,%2,%3}, {%4,%5,%6,%7}, {%8,%9}, {%0,%1,%2,%3};"
                 : "+f"(d[0]), "+f"(d[1]), "+f"(d[2]), "+f"(d[3])
                 : "r"(a.x), "r"(a.y), "r"(a.z), "r"(a.w), "r"(b0), "r"(b1));
}

__global__ void __launch_bounds__(NT, 2)
corr_mma_kernel(const float* __restrict__ inp,
                const float* __restrict__ sec,
                float* __restrict__ out)
{
    extern __shared__ char smem[];
    const int tid  = threadIdx.x;
    const int wid  = tid >> 5;
    const int lane = tid & 31;
    const int w0   = blockIdx.x * 16;
    const int c0   = blockIdx.y * MCH;
    const int b    = blockIdx.z;

    const int cbw = wid & 3;      // warp's channel block (16 ch)
    const int ntw = wid >> 2;     // warp's n-tile (8 px)

    // ---- stage sec row r into ring slot r%10, fragment-order layout ----
    auto stageA = [&](int r) {
        #pragma unroll
        for (int i = 0; i < 2; i++) {
            int idx = tid + i * NT;            // 384 = 4cb x 3s x 32l
            if (idx < 384) {
                int l  = idx & 31;
                int s  = (idx >> 5) % 3;
                int cb = idx / 96;
                int ch = cb * 16 + (l >> 2);
                int px = w0 - 4 + s * 8 + (l & 3);
                const float* base = sec + ((size_t)(b * CC + c0 + ch) * HH + r) * WW;
                float f0 = 0.f, f1 = 0.f, f2 = 0.f, f3 = 0.f;
                if ((unsigned)px < WW)       { f0 = __ldg(base + px);     f1 = __ldg(base + 8 * HW + px); }
                if ((unsigned)(px + 4) < WW) { f2 = __ldg(base + px + 4); f3 = __ldg(base + 8 * HW + px + 4); }
                uint4 v = make_uint4(f2tf(f0), f2tf(f1), f2tf(f2), f2tf(f3));
                *(uint4*)(smem + (r % 10) * RSLOT + (cb * 3 + s) * 512 + l * 16) = v;
            }
        }
    };

    // ---- build banded B tiles for output row hb into buffer bufsel ----
    auto buildB = [&](int hb, int bufsel) {
        #pragma unroll
        for (int i = 0; i < 3; i++) {
            int idx = tid + i * NT;            // 576 = 9p x 2nt x 32l
            if (idx < 576) {
                int l  = idx & 31;
                int nt = (idx >> 5) & 1;
                int p  = idx >> 6;
                int x  = 8 * nt + (l >> 2);
                int o0 = (l & 3) - (l >> 2);   // k(s=nt) - x
                const float* ib = inp + ((size_t)(b * 81 + p * 9) * HH + hb) * WW + (w0 + x);
                float g0 = ((unsigned)(o0)      <= 8u) ? __ldg(ib + (ptrdiff_t)(o0)      * HW) : 0.f;
                float g1 = ((unsigned)(o0 + 4)  <= 8u) ? __ldg(ib + (ptrdiff_t)(o0 + 4)  * HW) : 0.f;
                float g2 = ((unsigned)(o0 + 8)  <= 8u) ? __ldg(ib + (ptrdiff_t)(o0 + 8)  * HW) : 0.f;
                float g3 = ((unsigned)(o0 + 12) <= 8u) ? __ldg(ib + (ptrdiff_t)(o0 + 12) * HW) : 0.f;
                uint4 v = make_uint4(f2tf(g0), f2tf(g1), f2tf(g2), f2tf(g3));
                *(uint4*)(smem + B_OFF + bufsel * BBYTES + idx * 16) = v;
            }
        }
    };

    // prologue: sec rows 0..4, B for h=0 into buffer 0
    for (int r = 0; r < 5; r++) stageA(r);
    buildB(0, 0);
    __syncthreads();

    const unsigned aoff_warp = (unsigned)(cbw * 3 * 512 + lane * 16);
    const unsigned boff_lane = (unsigned)(ntw * 512 + lane * 16);
    const float sc = 1.0f / (float)CC;

    #pragma unroll 1
    for (int h = 0; h < HH; h++) {
        const int buf = h & 1;

        // ---- compute: warp = 16ch x 8px, two independent p-parity chains ----
        float accE[4] = {0.f, 0.f, 0.f, 0.f};
        float accO[4] = {0.f, 0.f, 0.f, 0.f};
        #pragma unroll
        for (int p = 0; p < 9; p++) {
            int r = h + p - MD;
            if ((unsigned)r < (unsigned)HH) {
                const char* ab = smem + (r % 10) * RSLOT + aoff_warp;
                uint4 A0 = *(const uint4*)(ab + ntw * 512);
                uint4 A1 = *(const uint4*)(ab + (ntw + 1) * 512);
                uint4 B0 = *(const uint4*)(smem + B_OFF + buf * BBYTES + p * 1024 + boff_lane);
                float* acc = (p & 1) ? accO : accE;
                mma8(acc, A0, B0.x, B0.y);    // k-frag s = ntw
                mma8(acc, A1, B0.z, B0.w);    // k-frag s = ntw+1
            }
        }

        // ---- epilogue: merge chains, scale + store ----
        {
            int cho = c0 + cbw * 16 + (lane >> 2);
            float* ob = out + ((size_t)(b * CC + cho) * HH + h) * WW + w0 + ntw * 8 + 2 * (lane & 3);
            *(float2*)(ob)          = make_float2((accE[0] + accO[0]) * sc, (accE[1] + accO[1]) * sc);
            *(float2*)(ob + 8 * HW) = make_float2((accE[2] + accO[2]) * sc, (accE[3] + accO[3]) * sc);
        }

        // ---- stage ahead: sec row h+5, B for h+1 ----
        if (h + 5 < HH) stageA(h + 5);
        if (h + 1 < HH) buildB(h + 1, buf ^ 1);
        __syncthreads();
    }
}

extern "C" void kernel_launch(void* const* d_in, const int* in_sizes, int n_in,
                              void* d_out, int out_size)
{
    const float* inp = (const float*)d_in[0];   // [B, 81, 128, 128]
    const float* sec = (const float*)d_in[1];   // [B, 256, 128, 128]
    float* out = (float*)d_out;                 // [B, 256, 128, 128]

    const int B = in_sizes[0] / (81 * HH * WW);

    cudaFuncSetAttribute(corr_mma_kernel,
                         cudaFuncAttributeMaxDynamicSharedMemorySize, SMEM_BYTES);

    dim3 grid(WW / 16, CC / MCH, B);   // (8, 4, 8) = 256 CTAs
    corr_mma_kernel<<<grid, NT, SMEM_BYTES>>>(inp, sec, out);
}

// round 13
// speedup vs baseline: 1.4304x; 1.2177x over previous
#include <cuda_runtime.h>
#include <cstdint>

// out[b,c,h,w] = (1/256) * sum_{p,o in 0..8} inp[b, p*9+o, h, w] * sec[b, c, h+p-4, w+o-4]
// B=8, C=256, H=W=128.
// mma.sync m16n8k8 tf32. CTA = 32ch x 16px x all h, NT=128 (4 warps), smem 48KB
// -> 4 CTAs/SM (4 barrier domains). Staging LDG prefetched into registers one
// iteration ahead; cvt+STS happen just before the barrier of the NEXT iteration.

#define HH 128
#define WW 128
#define CC 256
#define MD 4
#define HW (HH*WW)

#define NT 128
#define MCH 32
#define RSLOT (2*3*512)          // ring slot: 2 ch-blocks x 3 k-frags x 512B = 3072
#define RING_BYTES (10*RSLOT)    // 30720
#define B_OFF RING_BYTES
#define BBYTES (9*2*512)         // 9216 per buffer (9 p x 2 n-tiles x 512B)
#define SMEM_BYTES (B_OFF + 2*BBYTES)   // 49152

static __device__ __forceinline__ uint32_t f2tf(float f) {
    uint32_t r; asm("cvt.rna.tf32.f32 %0, %1;" : "=r"(r) : "f"(f)); return r;
}

static __device__ __forceinline__ void mma8(float* d, const uint4& a, uint32_t b0, uint32_t b1) {
    asm volatile("mma.sync.aligned.m16n8k8.row.col.f32.tf32.tf32.f32 "
                 "{%0,%1,%2,%3}, {%4,%5,%6,%7}, {%8,%9}, {%0,%1,%2,%3};"
                 : "+f"(d[0]), "+f"(d[1]), "+f"(d[2]), "+f"(d[3])
                 : "r"(a.x), "r"(a.y), "r"(a.z), "r"(a.w), "r"(b0), "r"(b1));
}

__global__ void __launch_bounds__(NT, 4)
corr_mma_kernel(const float* __restrict__ inp,
                const float* __restrict__ sec,
                float* __restrict__ out)
{
    extern __shared__ char smem[];
    const int tid  = threadIdx.x;
    const int wid  = tid >> 5;
    const int lane = tid & 31;
    const int w0   = blockIdx.x * 16;
    const int c0   = blockIdx.y * MCH;
    const int b    = blockIdx.z;

    const int cbw = wid & 1;      // warp's channel block (16 ch)
    const int ntw = wid >> 1;     // warp's n-tile (8 px)

    // ---- sec fragment load (gmem -> regs, raw f32) ----
    auto ldA = [&](int r, float4* pv) {
        #pragma unroll
        for (int i = 0; i < 2; i++) {
            int idx = tid + i * NT;            // 192 = 2cb x 3s x 32l
            if (idx < 192) {
                int l  = idx & 31;
                int s  = (idx >> 5) % 3;
                int cb = idx / 96;
                int ch = cb * 16 + (l >> 2);
                int px = w0 - 4 + s * 8 + (l & 3);
                const float* base = sec + ((size_t)(b * CC + c0 + ch) * HH + r) * WW;
                float f0 = 0.f, f1 = 0.f, f2 = 0.f, f3 = 0.f;
                if ((unsigned)px < WW)       { f0 = __ldg(base + px);     f1 = __ldg(base + 8 * HW + px); }
                if ((unsigned)(px + 4) < WW) { f2 = __ldg(base + px + 4); f3 = __ldg(base + 8 * HW + px + 4); }
                pv[i] = make_float4(f0, f1, f2, f3);
            }
        }
    };
    // ---- sec fragment store (regs -> ring slot, cvt at store time) ----
    auto stA = [&](int r, const float4* pv) {
        #pragma unroll
        for (int i = 0; i < 2; i++) {
            int idx = tid + i * NT;
            if (idx < 192) {
                int l  = idx & 31;
                int s  = (idx >> 5) % 3;
                int cb = idx / 96;
                uint4 v = make_uint4(f2tf(pv[i].x), f2tf(pv[i].y), f2tf(pv[i].z), f2tf(pv[i].w));
                *(uint4*)(smem + (r % 10) * RSLOT + (cb * 3 + s) * 512 + l * 16) = v;
            }
        }
    };

    // ---- banded B load (gmem -> regs) ----
    auto ldB = [&](int hb, float4* pv) {
        #pragma unroll
        for (int i = 0; i < 5; i++) {
            int idx = tid + i * NT;            // 576 = 9p x 2nt x 32l
            if (idx < 576) {
                int l  = idx & 31;
                int p  = idx >> 6;
                int x  = 8 * ((idx >> 5) & 1) + (l >> 2);
                int o0 = (l & 3) - (l >> 2);
                const float* ib = inp + ((size_t)(b * 81 + p * 9) * HH + hb) * WW + (w0 + x);
                float g0 = ((unsigned)(o0)      <= 8u) ? __ldg(ib + (ptrdiff_t)(o0)      * HW) : 0.f;
                float g1 = ((unsigned)(o0 + 4)  <= 8u) ? __ldg(ib + (ptrdiff_t)(o0 + 4)  * HW) : 0.f;
                float g2 = ((unsigned)(o0 + 8)  <= 8u) ? __ldg(ib + (ptrdiff_t)(o0 + 8)  * HW) : 0.f;
                float g3 = ((unsigned)(o0 + 12) <= 8u) ? __ldg(ib + (ptrdiff_t)(o0 + 12) * HW) : 0.f;
                pv[i] = make_float4(g0, g1, g2, g3);
            }
        }
    };
    // ---- banded B store (regs -> buffer, cvt at store time) ----
    auto stB = [&](int bufsel, const float4* pv) {
        #pragma unroll
        for (int i = 0; i < 5; i++) {
            int idx = tid + i * NT;
            if (idx < 576) {
                uint4 v = make_uint4(f2tf(pv[i].x), f2tf(pv[i].y), f2tf(pv[i].z), f2tf(pv[i].w));
                *(uint4*)(smem + B_OFF + bufsel * BBYTES + idx * 16) = v;
            }
        }
    };

    // ---- prologue: ring rows 0..4 + B(0) staged directly; pending = (row 5, B(1)) ----
    float4 pA[2], pB[5];
    for (int r = 0; r < 5; r++) { ldA(r, pA); stA(r, pA); }
    ldB(0, pB); stB(0, pB);
    ldA(5, pA);
    ldB(1, pB);
    __syncthreads();

    const unsigned aoff_warp = (unsigned)(cbw * 3 * 512 + lane * 16);
    const unsigned boff_lane = (unsigned)(ntw * 512 + lane * 16);
    const float sc = 1.0f / (float)CC;

    #pragma unroll 1
    for (int h = 0; h < HH; h++) {
        const int buf = h & 1;

        // step 1: STS pending (sec row h+5 -> ring, B(h+1) -> buf^1)
        if (h + 5 < HH) stA(h + 5, pA);
        if (h + 1 < HH) stB(buf ^ 1, pB);

        // step 2: prefetch next pending into regs (latency hidden by compute)
        if (h + 6 < HH) ldA(h + 6, pA);
        if (h + 2 < HH) ldB(h + 2, pB);

        // step 3: compute — warp = 16ch x 8px, two independent p-parity chains
        float accE[4] = {0.f, 0.f, 0.f, 0.f};
        float accO[4] = {0.f, 0.f, 0.f, 0.f};
        #pragma unroll
        for (int p = 0; p < 9; p++) {
            int r = h + p - MD;
            if ((unsigned)r < (unsigned)HH) {
                const char* ab = smem + (r % 10) * RSLOT + aoff_warp;
                uint4 A0 = *(const uint4*)(ab + ntw * 512);
                uint4 A1 = *(const uint4*)(ab + (ntw + 1) * 512);
                uint4 B0 = *(const uint4*)(smem + B_OFF + buf * BBYTES + p * 1024 + boff_lane);
                float* acc = (p & 1) ? accO : accE;
                mma8(acc, A0, B0.x, B0.y);
                mma8(acc, A1, B0.z, B0.w);
            }
        }

        // step 4: epilogue — merge chains, scale + store
        {
            int cho = c0 + cbw * 16 + (lane >> 2);
            float* ob = out + ((size_t)(b * CC + cho) * HH + h) * WW + w0 + ntw * 8 + 2 * (lane & 3);
            *(float2*)(ob)          = make_float2((accE[0] + accO[0]) * sc, (accE[1] + accO[1]) * sc);
            *(float2*)(ob + 8 * HW) = make_float2((accE[2] + accO[2]) * sc, (accE[3] + accO[3]) * sc);
        }

        // step 5: barrier — makes step-1 STS visible, protects buffers
        __syncthreads();
    }
}

extern "C" void kernel_launch(void* const* d_in, const int* in_sizes, int n_in,
                              void* d_out, int out_size)
{
    const float* inp = (const float*)d_in[0];   // [B, 81, 128, 128]
    const float* sec = (const float*)d_in[1];   // [B, 256, 128, 128]
    float* out = (float*)d_out;                 // [B, 256, 128, 128]

    const int B = in_sizes[0] / (81 * HH * WW);

    cudaFuncSetAttribute(corr_mma_kernel,
                         cudaFuncAttributeMaxDynamicSharedMemorySize, SMEM_BYTES);

    dim3 grid(WW / 16, CC / MCH, B);   // (8, 8, 8) = 512 CTAs
    corr_mma_kernel<<<grid, NT, SMEM_BYTES>>>(inp, sec, out);
}